// round 8
// baseline (speedup 1.0000x reference)
#include <cuda_runtime.h>
#include <cuda_bf16.h>
#include <cstdint>

// Problem constants
#define SS   128
#define BB   16
#define EE   512
#define HH   512
#define GG   2048
#define VV   32000
#define LNEPS 1e-5f
#define HPAD 514

// ---------------- scratch (device globals; 256B-aligned) ----------------
__device__ __align__(256) float g_xg[SS * BB * GG];     // (s,b,g) gate preacts
__device__ __align__(256) float g_hs[BB * SS * HH];     // hidden states
__device__ __align__(256) float g_hbuf[2][BB * HH];     // ping-pong h broadcast
__device__ __align__(256) unsigned g_cnt8[2048];        // 8 counters, 1KB apart
__device__ unsigned g_master;
__device__ unsigned g_bar_gen;
// bf16 split operands
__device__ __align__(256) __nv_bfloat16 g_nhi[BB * SS * HH];
__device__ __align__(256) __nv_bfloat16 g_nlo[BB * SS * HH];
__device__ __align__(256) __nv_bfloat16 g_whi[VV * HH];
__device__ __align__(256) __nv_bfloat16 g_wlo[VV * HH];
__device__ __align__(256) __nv_bfloat16 g_ahi[SS * BB * EE];
__device__ __align__(256) __nv_bfloat16 g_alo[SS * BB * EE];
__device__ __align__(256) __nv_bfloat16 g_ihhi[GG * EE];
__device__ __align__(256) __nv_bfloat16 g_ihlo[GG * EE];

__device__ __forceinline__ float sigf(float x) { return 1.0f / (1.0f + __expf(-x)); }
__device__ __forceinline__ float tanhfast(float x) { return 2.0f / (1.0f + __expf(-2.0f * x)) - 1.0f; }

__device__ __forceinline__ uint32_t smem_u32(const void* p) {
    uint32_t a;
    asm("{ .reg .u64 t; cvta.to.shared.u64 t, %1; cvt.u32.u64 %0, t; }" : "=r"(a) : "l"(p));
    return a;
}

__device__ __forceinline__ void split_bf16(float v, __nv_bfloat16& h, __nv_bfloat16& l) {
    h = __float2bfloat16_rn(v);
    l = __float2bfloat16_rn(v - __bfloat162float(h));
}

// ============================================================================
// fp32 -> bf16 hi/lo split (grid-stride, float4)
// ============================================================================
__global__ __launch_bounds__(256) void conv_split(
    const float* __restrict__ src, __nv_bfloat16* __restrict__ dhi,
    __nv_bfloat16* __restrict__ dlo, unsigned total4)
{
    const float4* s4 = (const float4*)src;
    for (unsigned p = blockIdx.x * blockDim.x + threadIdx.x; p < total4;
         p += gridDim.x * blockDim.x) {
        float4 v = s4[p];
        __nv_bfloat16 h0, h1, h2, h3, l0, l1, l2, l3;
        split_bf16(v.x, h0, l0); split_bf16(v.y, h1, l1);
        split_bf16(v.z, h2, l2); split_bf16(v.w, h3, l3);
        ((__nv_bfloat162*)dhi)[p * 2 + 0] = __nv_bfloat162(h0, h1);
        ((__nv_bfloat162*)dhi)[p * 2 + 1] = __nv_bfloat162(h2, h3);
        ((__nv_bfloat162*)dlo)[p * 2 + 0] = __nv_bfloat162(l0, l1);
        ((__nv_bfloat162*)dlo)[p * 2 + 1] = __nv_bfloat162(l2, l3);
    }
}

// ============================================================================
// Embedding gather + bf16 hi/lo split. Row m -> token x[(m&15)*SS + (m>>4)].
// ============================================================================
__global__ __launch_bounds__(128) void conv_emb(
    const float* __restrict__ emb, const int* __restrict__ x)
{
    const int m = blockIdx.x;
    const int tid = threadIdx.x;
    const int token = x[(m & 15) * SS + (m >> 4)];
    float4 v = *(const float4*)(emb + (size_t)token * 512 + tid * 4);
    __nv_bfloat16 h0, h1, h2, h3, l0, l1, l2, l3;
    split_bf16(v.x, h0, l0); split_bf16(v.y, h1, l1);
    split_bf16(v.z, h2, l2); split_bf16(v.w, h3, l3);
    ((__nv_bfloat162*)(g_ahi + (size_t)m * 512))[tid * 2 + 0] = __nv_bfloat162(h0, h1);
    ((__nv_bfloat162*)(g_ahi + (size_t)m * 512))[tid * 2 + 1] = __nv_bfloat162(h2, h3);
    ((__nv_bfloat162*)(g_alo + (size_t)m * 512))[tid * 2 + 0] = __nv_bfloat162(l0, l1);
    ((__nv_bfloat162*)(g_alo + (size_t)m * 512))[tid * 2 + 1] = __nv_bfloat162(l2, l3);
}

// ============================================================================
// Persistent LSTM recurrence — hierarchical atomic barrier
// (release structure identical to proven R7: all-thread threadfence ->
//  syncthreads -> tid0 atomics; only arrival aggregation is split 8-way)
// ============================================================================
__global__ __launch_bounds__(256, 1) void lstm_kernel(
    const float* __restrict__ Whh,
    const float* __restrict__ z,
    float* __restrict__ out_hc)
{
    extern __shared__ float sm[];
    float* Wsm = sm;
    float* hsm = Wsm + 16 * HPAD;
    float* red = hsm + 16 * HPAD;
    float* pre = red + 4096;
    float* cst = pre + 256;

    const int tid = threadIdx.x;
    const int cta = blockIdx.x;

    unsigned gen0 = 0;
    if (tid == 0) gen0 = *((volatile unsigned*)&g_bar_gen);

    for (int i = tid; i < 16 * 128; i += 256) {
        int r = i >> 7;
        int e4 = (i & 127) * 4;
        int grow = (r >> 2) * 512 + cta * 4 + (r & 3);
        float4 w = *(const float4*)(Whh + (size_t)grow * 512 + e4);
        float* dst = &Wsm[r * HPAD + e4];
        dst[0] = w.x; dst[1] = w.y; dst[2] = w.z; dst[3] = w.w;
    }
    for (int i = tid; i < 16 * 128; i += 256) {
        int b = i >> 7;
        int e4 = (i & 127) * 4;
        float4 h = *(const float4*)(z + b * 1024 + e4);
        float* dst = &hsm[b * HPAD + e4];
        dst[0] = h.x; dst[1] = h.y; dst[2] = h.z; dst[3] = h.w;
    }
    if (tid < 64) {
        int ul = tid >> 4, b = tid & 15;
        cst[ul * 16 + b] = z[b * 1024 + 512 + cta * 4 + ul];
    }
    __syncthreads();

    const int kq = tid >> 4;
    const int rq = (tid >> 2) & 3;
    const int bq = tid & 3;

    for (int t = 0; t < SS; t++) {
        float acc00=0,acc01=0,acc02=0,acc03=0;
        float acc10=0,acc11=0,acc12=0,acc13=0;
        float acc20=0,acc21=0,acc22=0,acc23=0;
        float acc30=0,acc31=0,acc32=0,acc33=0;
        const float* h0p = &hsm[(bq * 4 + 0) * HPAD];
        const float* h1p = &hsm[(bq * 4 + 1) * HPAD];
        const float* h2p = &hsm[(bq * 4 + 2) * HPAD];
        const float* h3p = &hsm[(bq * 4 + 3) * HPAD];
        const float* w0p = &Wsm[(rq * 4 + 0) * HPAD];
        const float* w1p = &Wsm[(rq * 4 + 1) * HPAD];
        const float* w2p = &Wsm[(rq * 4 + 2) * HPAD];
        const float* w3p = &Wsm[(rq * 4 + 3) * HPAD];
#pragma unroll 4
        for (int j = 0; j < 16; j++) {
            int e = (kq + 16 * j) * 2;
            float2 hv0 = *(const float2*)(h0p + e);
            float2 hv1 = *(const float2*)(h1p + e);
            float2 hv2 = *(const float2*)(h2p + e);
            float2 hv3 = *(const float2*)(h3p + e);
            float2 wv;
            wv = *(const float2*)(w0p + e);
            acc00 += wv.x*hv0.x + wv.y*hv0.y; acc01 += wv.x*hv1.x + wv.y*hv1.y;
            acc02 += wv.x*hv2.x + wv.y*hv2.y; acc03 += wv.x*hv3.x + wv.y*hv3.y;
            wv = *(const float2*)(w1p + e);
            acc10 += wv.x*hv0.x + wv.y*hv0.y; acc11 += wv.x*hv1.x + wv.y*hv1.y;
            acc12 += wv.x*hv2.x + wv.y*hv2.y; acc13 += wv.x*hv3.x + wv.y*hv3.y;
            wv = *(const float2*)(w2p + e);
            acc20 += wv.x*hv0.x + wv.y*hv0.y; acc21 += wv.x*hv1.x + wv.y*hv1.y;
            acc22 += wv.x*hv2.x + wv.y*hv2.y; acc23 += wv.x*hv3.x + wv.y*hv3.y;
            wv = *(const float2*)(w3p + e);
            acc30 += wv.x*hv0.x + wv.y*hv0.y; acc31 += wv.x*hv1.x + wv.y*hv1.y;
            acc32 += wv.x*hv2.x + wv.y*hv2.y; acc33 += wv.x*hv3.x + wv.y*hv3.y;
        }
        {
            float* rbase = &red[kq * 256];
            int r0 = rq * 4, b0 = bq * 4;
            rbase[(r0+0)*16 + b0+0]=acc00; rbase[(r0+0)*16 + b0+1]=acc01; rbase[(r0+0)*16 + b0+2]=acc02; rbase[(r0+0)*16 + b0+3]=acc03;
            rbase[(r0+1)*16 + b0+0]=acc10; rbase[(r0+1)*16 + b0+1]=acc11; rbase[(r0+1)*16 + b0+2]=acc12; rbase[(r0+1)*16 + b0+3]=acc13;
            rbase[(r0+2)*16 + b0+0]=acc20; rbase[(r0+2)*16 + b0+1]=acc21; rbase[(r0+2)*16 + b0+2]=acc22; rbase[(r0+2)*16 + b0+3]=acc23;
            rbase[(r0+3)*16 + b0+0]=acc30; rbase[(r0+3)*16 + b0+1]=acc31; rbase[(r0+3)*16 + b0+2]=acc32; rbase[(r0+3)*16 + b0+3]=acc33;
        }
        __syncthreads();

        {
            int r = tid >> 4, b = tid & 15;
            float s = 0.0f;
#pragma unroll
            for (int k2 = 0; k2 < 16; k2++) s += red[k2 * 256 + r * 16 + b];
            int q = r >> 2, ul = r & 3;
            s += __ldg(&g_xg[(size_t)(t * 16 + b) * 2048 + q * 512 + cta * 4 + ul]);
            pre[r * 16 + b] = s;
        }
        __syncthreads();

        if (tid < 64) {
            int ul = tid >> 4, b = tid & 15;
            int ug = cta * 4 + ul;
            float iv = pre[(0  + ul) * 16 + b];
            float fv = pre[(4  + ul) * 16 + b];
            float gv = pre[(8  + ul) * 16 + b];
            float ov = pre[(12 + ul) * 16 + b];
            float c = cst[ul * 16 + b];
            c = sigf(fv) * c + sigf(iv) * tanhfast(gv);
            float hN = sigf(ov) * tanhfast(c);
            cst[ul * 16 + b] = c;
            g_hbuf[t & 1][b * 512 + ug] = hN;
            g_hs[(size_t)b * (SS * HH) + t * 512 + ug] = hN;
            if (t == SS - 1) {
                out_hc[b * 1024 + ug] = hN;
                out_hc[b * 1024 + 512 + ug] = c;
            }
        }

        if (t < SS - 1) {
            __threadfence();
            __syncthreads();
            if (tid == 0) {
                unsigned target = gen0 + (unsigned)t + 1u;
                unsigned a = atomicAdd(&g_cnt8[(cta & 7) << 8], 1u);
                if (a == 15u) {
                    unsigned m = atomicAdd(&g_master, 1u);
                    if (m == 7u) {
                        // all 128 arrived; reset before fenced gen bump
#pragma unroll
                        for (int q = 0; q < 8; q++)
                            atomicExch(&g_cnt8[q << 8], 0u);
                        atomicExch(&g_master, 0u);
                        __threadfence();
                        atomicAdd(&g_bar_gen, 1u);
                    }
                }
                while ((int)(*((volatile unsigned*)&g_bar_gen) - target) < 0) { }
            }
            __syncthreads();
            // reload h broadcast (bypass L1)
            const float2* src = (const float2*)(&g_hbuf[t & 1][0]);
            for (int i = tid; i < 4096; i += 256) {
                int b = i >> 8;
                int e2 = i & 255;
                float2 v = __ldcg(src + i);
                *(float2*)&hsm[b * HPAD + e2 * 2] = v;
            }
            __syncthreads();
        }
    }
}

// ============================================================================
// LayerNorm -> bf16 hi/lo split outputs
// ============================================================================
__global__ __launch_bounds__(128) void ln_kernel(
    const float* __restrict__ gamma, const float* __restrict__ beta)
{
    __shared__ float rs[4], rs2[4];
    const int m = blockIdx.x;
    const int tid = threadIdx.x;
    const float* row = g_hs + (size_t)m * 512;

    float4 v = *(const float4*)(row + tid * 4);
    float s  = v.x + v.y + v.z + v.w;
    float s2 = v.x * v.x + v.y * v.y + v.z * v.z + v.w * v.w;

    const int lane = tid & 31, w = tid >> 5;
#pragma unroll
    for (int o = 16; o; o >>= 1) {
        s  += __shfl_xor_sync(0xffffffffu, s, o);
        s2 += __shfl_xor_sync(0xffffffffu, s2, o);
    }
    if (lane == 0) { rs[w] = s; rs2[w] = s2; }
    __syncthreads();
    s  = rs[0] + rs[1] + rs[2] + rs[3];
    s2 = rs2[0] + rs2[1] + rs2[2] + rs2[3];

    float mu = s * (1.0f / 512.0f);
    float var = s2 * (1.0f / 512.0f) - mu * mu;
    float inv = rsqrtf(var + LNEPS);

    float4 g4 = *(const float4*)(gamma + tid * 4);
    float4 b4 = *(const float4*)(beta + tid * 4);
    float o0 = (v.x - mu) * inv * g4.x + b4.x;
    float o1 = (v.y - mu) * inv * g4.y + b4.y;
    float o2 = (v.z - mu) * inv * g4.z + b4.z;
    float o3 = (v.w - mu) * inv * g4.w + b4.w;

    __nv_bfloat16 h0, h1, h2, h3, l0, l1, l2, l3;
    split_bf16(o0, h0, l0); split_bf16(o1, h1, l1);
    split_bf16(o2, h2, l2); split_bf16(o3, h3, l3);

    __nv_bfloat162* hp = (__nv_bfloat162*)(g_nhi + (size_t)m * 512);
    __nv_bfloat162* lp = (__nv_bfloat162*)(g_nlo + (size_t)m * 512);
    hp[tid * 2 + 0] = __nv_bfloat162(h0, h1);
    hp[tid * 2 + 1] = __nv_bfloat162(h2, h3);
    lp[tid * 2 + 0] = __nv_bfloat162(l0, l1);
    lp[tid * 2 + 1] = __nv_bfloat162(l2, l3);
}

// ============================================================================
// mma.sync bf16-split GEMM: C[M x N] = A @ B^T + bias0 (+ bias1)
// CTA tile 128x256, warp tile 64x64, K=512 in 16 chunks of 32, 3-stage cp.async.
// SMEM stage: A 16KB @ 0, B 32KB @ 16384. Row = 128B [k hi | k lo], swizzled.
// ============================================================================
#define GS_STAGE 49152
#define FC_NCHUNK 16

__device__ __forceinline__ void ldsm_x4(uint32_t& r0, uint32_t& r1, uint32_t& r2,
                                        uint32_t& r3, uint32_t addr) {
    asm volatile("ldmatrix.sync.aligned.m8n8.x4.shared.b16 {%0,%1,%2,%3}, [%4];"
                 : "=r"(r0), "=r"(r1), "=r"(r2), "=r"(r3) : "r"(addr));
}

__device__ __forceinline__ void mma_bf16(float* c, const uint32_t* a, const uint32_t* b) {
    asm volatile(
        "mma.sync.aligned.m16n8k16.row.col.f32.bf16.bf16.f32 "
        "{%0,%1,%2,%3}, {%4,%5,%6,%7}, {%8,%9}, {%0,%1,%2,%3};"
        : "+f"(c[0]), "+f"(c[1]), "+f"(c[2]), "+f"(c[3])
        : "r"(a[0]), "r"(a[1]), "r"(a[2]), "r"(a[3]), "r"(b[0]), "r"(b[1]));
}

__global__ __launch_bounds__(256, 1) void gemm_mma(
    const __nv_bfloat16* __restrict__ Ahi, const __nv_bfloat16* __restrict__ Alo,
    const __nv_bfloat16* __restrict__ Bhi, const __nv_bfloat16* __restrict__ Blo,
    const float* __restrict__ bias0, const float* __restrict__ bias1,
    float* __restrict__ C, int N)
{
    extern __shared__ char smem[];
    const uint32_t sb = smem_u32(smem);
    const int tid = threadIdx.x;
    const int wid = tid >> 5;
    const int lane = tid & 31;
    const int m0 = blockIdx.x * 128;
    const int n0 = blockIdx.y * 256;
    const int warp_m = wid >> 2;   // 0..1 (64 m each)
    const int warp_n = wid & 3;    // 0..3 (64 n each)

    // ---- cp.async loader: A 1024 + B 2048 x 16B per chunk = 12 per thread ----
    auto load_chunk = [&](int c) {
        const int k0 = c * 32;
        const uint32_t st = sb + (uint32_t)(c % 3) * GS_STAGE;
#pragma unroll
        for (int it = 0; it < 12; it++) {
            int i = it * 256 + tid;         // 0..3071
            if (i < 1024) {
                int row = i >> 3;           // 0..127
                int g = i & 7;
                int part = g >> 2;
                int kg = g & 3;
                const __nv_bfloat16* src =
                    (part ? Alo : Ahi) + (size_t)(m0 + row) * 512 + k0 + kg * 8;
                uint32_t dst = st + (uint32_t)(row * 128) +
                               ((uint32_t)(g ^ (row & 7)) << 4);
                asm volatile("cp.async.cg.shared.global [%0], [%1], 16;" :: "r"(dst), "l"(src));
            } else {
                int li = i - 1024;
                int row = li >> 3;          // 0..255
                int g = li & 7;
                int part = g >> 2;
                int kg = g & 3;
                const __nv_bfloat16* src =
                    (part ? Blo : Bhi) + (size_t)(n0 + row) * 512 + k0 + kg * 8;
                uint32_t dst = st + 16384u + (uint32_t)(row * 128) +
                               ((uint32_t)(g ^ (row & 7)) << 4);
                asm volatile("cp.async.cg.shared.global [%0], [%1], 16;" :: "r"(dst), "l"(src));
            }
        }
        asm volatile("cp.async.commit_group;" ::: "memory");
    };

    load_chunk(0);
    load_chunk(1);

    const int t = lane >> 3, trow = lane & 7;
    const int a_mpart = (t & 1) * 8 + trow;
    const int a_gsel = t >> 1;
    uint32_t a_row_off[4]; uint32_t a_sw[4];
#pragma unroll
    for (int mf = 0; mf < 4; mf++) {
        int ml = warp_m * 64 + mf * 16 + a_mpart;
        a_row_off[mf] = (uint32_t)(ml * 128);
        a_sw[mf] = (uint32_t)(ml & 7);
    }
    const int b_fragsel = t >> 1;
    const int b_gsel = t & 1;
    uint32_t b_row_off[4]; uint32_t b_sw[4];
#pragma unroll
    for (int nf2 = 0; nf2 < 4; nf2++) {
        int nl = warp_n * 64 + (nf2 * 2 + b_fragsel) * 8 + trow;
        b_row_off[nf2] = (uint32_t)(nl * 128) + 16384u;
        b_sw[nf2] = (uint32_t)(nl & 7);
    }

    float acc[4][8][4];
#pragma unroll
    for (int i = 0; i < 4; i++)
#pragma unroll
        for (int j = 0; j < 8; j++)
#pragma unroll
            for (int r = 0; r < 4; r++) acc[i][j][r] = 0.0f;

    for (int c = 0; c < FC_NCHUNK; c++) {
        if (c < FC_NCHUNK - 1)
            asm volatile("cp.async.wait_group 1;" ::: "memory");
        else
            asm volatile("cp.async.wait_group 0;" ::: "memory");
        __syncthreads();
        if (c + 2 < FC_NCHUNK) load_chunk(c + 2);

        const uint32_t st = sb + (uint32_t)(c % 3) * GS_STAGE;
#pragma unroll
        for (int ks = 0; ks < 2; ks++) {
            uint32_t ah[4][4], al[4][4];
#pragma unroll
            for (int mf = 0; mf < 4; mf++) {
                uint32_t Ghi = (uint32_t)(ks * 2 + a_gsel);
                uint32_t Glo = Ghi + 4u;
                ldsm_x4(ah[mf][0], ah[mf][1], ah[mf][2], ah[mf][3],
                        st + a_row_off[mf] + ((Ghi ^ a_sw[mf]) << 4));
                ldsm_x4(al[mf][0], al[mf][1], al[mf][2], al[mf][3],
                        st + a_row_off[mf] + ((Glo ^ a_sw[mf]) << 4));
            }
#pragma unroll
            for (int nf2 = 0; nf2 < 4; nf2++) {
                uint32_t bh[2][2], bl[2][2];
                uint32_t Ghi = (uint32_t)(ks * 2 + b_gsel);
                uint32_t Glo = Ghi + 4u;
                ldsm_x4(bh[0][0], bh[0][1], bh[1][0], bh[1][1],
                        st + b_row_off[nf2] + ((Ghi ^ b_sw[nf2]) << 4));
                ldsm_x4(bl[0][0], bl[0][1], bl[1][0], bl[1][1],
                        st + b_row_off[nf2] + ((Glo ^ b_sw[nf2]) << 4));
#pragma unroll
                for (int mf = 0; mf < 4; mf++)
#pragma unroll
                    for (int j = 0; j < 2; j++) {
                        float* a4 = acc[mf][nf2 * 2 + j];
                        mma_bf16(a4, ah[mf], bh[j]);
                        mma_bf16(a4, al[mf], bh[j]);
                        mma_bf16(a4, ah[mf], bl[j]);
                    }
            }
        }
    }

    // ---- epilogue: direct global stores with bias ----
    const int lrow = lane >> 2;
    const int lcol = (lane & 3) * 2;
#pragma unroll
    for (int mf = 0; mf < 4; mf++) {
        int r0 = m0 + warp_m * 64 + mf * 16 + lrow;
        float* crow0 = C + (size_t)r0 * N;
        float* crow1 = crow0 + (size_t)8 * N;
#pragma unroll
        for (int nf = 0; nf < 8; nf++) {
            int cn = n0 + warp_n * 64 + nf * 8 + lcol;
            float b0 = __ldg(bias0 + cn);
            float b1 = __ldg(bias0 + cn + 1);
            if (bias1) { b0 += __ldg(bias1 + cn); b1 += __ldg(bias1 + cn + 1); }
            float2 v0 = { acc[mf][nf][0] + b0, acc[mf][nf][1] + b1 };
            float2 v1 = { acc[mf][nf][2] + b0, acc[mf][nf][3] + b1 };
            *(float2*)(crow0 + cn) = v0;
            *(float2*)(crow1 + cn) = v1;
        }
    }
}

// ============================================================================
// launch
// ============================================================================
extern "C" void kernel_launch(void* const* d_in, const int* in_sizes, int n_in,
                              void* d_out, int out_size)
{
    const int*   x    = (const int*)d_in[0];
    const float* z    = (const float*)d_in[1];
    const float* emb  = (const float*)d_in[2];
    const float* W_ih = (const float*)d_in[3];
    const float* W_hh = (const float*)d_in[4];
    const float* b_ih = (const float*)d_in[5];
    const float* b_hh = (const float*)d_in[6];
    const float* ln_g = (const float*)d_in[7];
    const float* ln_b = (const float*)d_in[8];
    const float* fc_W = (const float*)d_in[9];
    const float* fc_b = (const float*)d_in[10];
    float* out = (float*)d_out;

    float* xg_p;
    __nv_bfloat16 *whi_p, *wlo_p, *ahi_p, *alo_p, *ihhi_p, *ihlo_p, *nhi_p, *nlo_p;
    cudaGetSymbolAddress((void**)&xg_p, g_xg);
    cudaGetSymbolAddress((void**)&whi_p, g_whi);
    cudaGetSymbolAddress((void**)&wlo_p, g_wlo);
    cudaGetSymbolAddress((void**)&ahi_p, g_ahi);
    cudaGetSymbolAddress((void**)&alo_p, g_alo);
    cudaGetSymbolAddress((void**)&ihhi_p, g_ihhi);
    cudaGetSymbolAddress((void**)&ihlo_p, g_ihlo);
    cudaGetSymbolAddress((void**)&nhi_p, g_nhi);
    cudaGetSymbolAddress((void**)&nlo_p, g_nlo);

    const int gemm_smem = 3 * GS_STAGE;   // 147456
    cudaFuncSetAttribute(gemm_mma, cudaFuncAttributeMaxDynamicSharedMemorySize, gemm_smem);

    // K0a: fc_W -> bf16 hi/lo
    conv_split<<<2048, 256>>>(fc_W, whi_p, wlo_p, (unsigned)(VV * HH / 4));
    // K0b: W_ih -> bf16 hi/lo
    conv_split<<<256, 256>>>(W_ih, ihhi_p, ihlo_p, (unsigned)(GG * EE / 4));
    // K0c: gathered embedding -> bf16 hi/lo
    conv_emb<<<SS * BB, 128>>>(emb, x);

    // K1: input-side gate GEMM on tensor cores -> g_xg
    {
        dim3 grid((SS * BB) / 128, GG / 256);  // (16, 8) — single wave
        gemm_mma<<<grid, 256, gemm_smem>>>(ahi_p, alo_p, ihhi_p, ihlo_p,
                                           b_ih, b_hh, xg_p, GG);
    }

    // K2: persistent LSTM recurrence
    {
        const int smem = (16 * HPAD * 2 + 4096 + 256 + 64) * 4;
        cudaFuncSetAttribute(lstm_kernel, cudaFuncAttributeMaxDynamicSharedMemorySize, smem);
        lstm_kernel<<<128, 256, smem>>>(W_hh, z, out + (size_t)BB * SS * VV);
    }

    // K3: layernorm -> bf16 hi/lo
    ln_kernel<<<BB * SS, 128>>>(ln_g, ln_b);

    // K4: FC logits GEMM on tensor cores
    {
        dim3 grid((SS * BB) / 128, VV / 256);  // (16, 125)
        gemm_mma<<<grid, 256, gemm_smem>>>(nhi_p, nlo_p, whi_p, wlo_p,
                                           fc_b, nullptr, out, VV);
    }
}

// round 9
// speedup vs baseline: 1.0192x; 1.0192x over previous
#include <cuda_runtime.h>
#include <cuda_bf16.h>
#include <cstdint>

// Problem constants
#define SS   128
#define BB   16
#define EE   512
#define HH   512
#define GG   2048
#define VV   32000
#define LNEPS 1e-5f
#define HPAD 514

// ---------------- scratch (device globals; 256B-aligned) ----------------
__device__ __align__(256) float g_xg[SS * BB * GG];     // (s,b,g) gate preacts
__device__ __align__(256) float g_hs[BB * SS * HH];     // hidden states
__device__ __align__(256) float g_hbuf[2][BB * HH];     // ping-pong h broadcast
__device__ __align__(256) unsigned g_cnt8[2048];        // 8 counters, 1KB apart
__device__ unsigned g_master;
__device__ unsigned g_bar_gen;
// bf16 split operands
__device__ __align__(256) __nv_bfloat16 g_nhi[BB * SS * HH];
__device__ __align__(256) __nv_bfloat16 g_nlo[BB * SS * HH];
__device__ __align__(256) __nv_bfloat16 g_whi[VV * HH];
__device__ __align__(256) __nv_bfloat16 g_wlo[VV * HH];
__device__ __align__(256) __nv_bfloat16 g_ahi[SS * BB * EE];
__device__ __align__(256) __nv_bfloat16 g_alo[SS * BB * EE];
__device__ __align__(256) __nv_bfloat16 g_ihhi[GG * EE];
__device__ __align__(256) __nv_bfloat16 g_ihlo[GG * EE];

__device__ __forceinline__ float sigf(float x) { return 1.0f / (1.0f + __expf(-x)); }
__device__ __forceinline__ float tanhfast(float x) { return 2.0f / (1.0f + __expf(-2.0f * x)) - 1.0f; }

__device__ __forceinline__ uint32_t smem_u32(const void* p) {
    uint32_t a;
    asm("{ .reg .u64 t; cvta.to.shared.u64 t, %1; cvt.u32.u64 %0, t; }" : "=r"(a) : "l"(p));
    return a;
}

__device__ __forceinline__ void split_bf16(float v, __nv_bfloat16& h, __nv_bfloat16& l) {
    h = __float2bfloat16_rn(v);
    l = __float2bfloat16_rn(v - __bfloat162float(h));
}

// ============================================================================
// fp32 -> bf16 hi/lo split (grid-stride, float4)
// ============================================================================
__global__ __launch_bounds__(256) void conv_split(
    const float* __restrict__ src, __nv_bfloat16* __restrict__ dhi,
    __nv_bfloat16* __restrict__ dlo, unsigned total4)
{
    const float4* s4 = (const float4*)src;
    for (unsigned p = blockIdx.x * blockDim.x + threadIdx.x; p < total4;
         p += gridDim.x * blockDim.x) {
        float4 v = s4[p];
        __nv_bfloat16 h0, h1, h2, h3, l0, l1, l2, l3;
        split_bf16(v.x, h0, l0); split_bf16(v.y, h1, l1);
        split_bf16(v.z, h2, l2); split_bf16(v.w, h3, l3);
        ((__nv_bfloat162*)dhi)[p * 2 + 0] = __nv_bfloat162(h0, h1);
        ((__nv_bfloat162*)dhi)[p * 2 + 1] = __nv_bfloat162(h2, h3);
        ((__nv_bfloat162*)dlo)[p * 2 + 0] = __nv_bfloat162(l0, l1);
        ((__nv_bfloat162*)dlo)[p * 2 + 1] = __nv_bfloat162(l2, l3);
    }
}

// ============================================================================
// Embedding gather + bf16 hi/lo split. Row m -> token x[(m&15)*SS + (m>>4)].
// ============================================================================
__global__ __launch_bounds__(128) void conv_emb(
    const float* __restrict__ emb, const int* __restrict__ x)
{
    const int m = blockIdx.x;
    const int tid = threadIdx.x;
    const int token = x[(m & 15) * SS + (m >> 4)];
    float4 v = *(const float4*)(emb + (size_t)token * 512 + tid * 4);
    __nv_bfloat16 h0, h1, h2, h3, l0, l1, l2, l3;
    split_bf16(v.x, h0, l0); split_bf16(v.y, h1, l1);
    split_bf16(v.z, h2, l2); split_bf16(v.w, h3, l3);
    ((__nv_bfloat162*)(g_ahi + (size_t)m * 512))[tid * 2 + 0] = __nv_bfloat162(h0, h1);
    ((__nv_bfloat162*)(g_ahi + (size_t)m * 512))[tid * 2 + 1] = __nv_bfloat162(h2, h3);
    ((__nv_bfloat162*)(g_alo + (size_t)m * 512))[tid * 2 + 0] = __nv_bfloat162(l0, l1);
    ((__nv_bfloat162*)(g_alo + (size_t)m * 512))[tid * 2 + 1] = __nv_bfloat162(l2, l3);
}

// ============================================================================
// Persistent LSTM recurrence — hierarchical atomic barrier + xg prefetch
// ============================================================================
__global__ __launch_bounds__(256, 1) void lstm_kernel(
    const float* __restrict__ Whh,
    const float* __restrict__ z,
    float* __restrict__ out_hc)
{
    extern __shared__ float sm[];
    float* Wsm = sm;
    float* hsm = Wsm + 16 * HPAD;
    float* red = hsm + 16 * HPAD;
    float* pre = red + 4096;
    float* cst = pre + 256;

    const int tid = threadIdx.x;
    const int cta = blockIdx.x;

    unsigned gen0 = 0;
    if (tid == 0) gen0 = *((volatile unsigned*)&g_bar_gen);

    for (int i = tid; i < 16 * 128; i += 256) {
        int r = i >> 7;
        int e4 = (i & 127) * 4;
        int grow = (r >> 2) * 512 + cta * 4 + (r & 3);
        float4 w = *(const float4*)(Whh + (size_t)grow * 512 + e4);
        float* dst = &Wsm[r * HPAD + e4];
        dst[0] = w.x; dst[1] = w.y; dst[2] = w.z; dst[3] = w.w;
    }
    for (int i = tid; i < 16 * 128; i += 256) {
        int b = i >> 7;
        int e4 = (i & 127) * 4;
        float4 h = *(const float4*)(z + b * 1024 + e4);
        float* dst = &hsm[b * HPAD + e4];
        dst[0] = h.x; dst[1] = h.y; dst[2] = h.z; dst[3] = h.w;
    }
    if (tid < 64) {
        int ul = tid >> 4, b = tid & 15;
        cst[ul * 16 + b] = z[b * 1024 + 512 + cta * 4 + ul];
    }
    __syncthreads();

    const int kq = tid >> 4;
    const int rq = (tid >> 2) & 3;
    const int bq = tid & 3;
    // xg address for the reduce phase (r = tid>>4, b = tid&15)
    const int xr = tid >> 4, xb = tid & 15;
    const float* xg_addr = &g_xg[(size_t)xb * 2048 + (xr >> 2) * 512 + cta * 4 + (xr & 3)];

    for (int t = 0; t < SS; t++) {
        // prefetch this step's xg early (used after the reduce sync)
        float xg_v = __ldg(xg_addr + (size_t)t * 16 * 2048);

        float acc00=0,acc01=0,acc02=0,acc03=0;
        float acc10=0,acc11=0,acc12=0,acc13=0;
        float acc20=0,acc21=0,acc22=0,acc23=0;
        float acc30=0,acc31=0,acc32=0,acc33=0;
        const float* h0p = &hsm[(bq * 4 + 0) * HPAD];
        const float* h1p = &hsm[(bq * 4 + 1) * HPAD];
        const float* h2p = &hsm[(bq * 4 + 2) * HPAD];
        const float* h3p = &hsm[(bq * 4 + 3) * HPAD];
        const float* w0p = &Wsm[(rq * 4 + 0) * HPAD];
        const float* w1p = &Wsm[(rq * 4 + 1) * HPAD];
        const float* w2p = &Wsm[(rq * 4 + 2) * HPAD];
        const float* w3p = &Wsm[(rq * 4 + 3) * HPAD];
#pragma unroll 4
        for (int j = 0; j < 16; j++) {
            int e = (kq + 16 * j) * 2;
            float2 hv0 = *(const float2*)(h0p + e);
            float2 hv1 = *(const float2*)(h1p + e);
            float2 hv2 = *(const float2*)(h2p + e);
            float2 hv3 = *(const float2*)(h3p + e);
            float2 wv;
            wv = *(const float2*)(w0p + e);
            acc00 += wv.x*hv0.x + wv.y*hv0.y; acc01 += wv.x*hv1.x + wv.y*hv1.y;
            acc02 += wv.x*hv2.x + wv.y*hv2.y; acc03 += wv.x*hv3.x + wv.y*hv3.y;
            wv = *(const float2*)(w1p + e);
            acc10 += wv.x*hv0.x + wv.y*hv0.y; acc11 += wv.x*hv1.x + wv.y*hv1.y;
            acc12 += wv.x*hv2.x + wv.y*hv2.y; acc13 += wv.x*hv3.x + wv.y*hv3.y;
            wv = *(const float2*)(w2p + e);
            acc20 += wv.x*hv0.x + wv.y*hv0.y; acc21 += wv.x*hv1.x + wv.y*hv1.y;
            acc22 += wv.x*hv2.x + wv.y*hv2.y; acc23 += wv.x*hv3.x + wv.y*hv3.y;
            wv = *(const float2*)(w3p + e);
            acc30 += wv.x*hv0.x + wv.y*hv0.y; acc31 += wv.x*hv1.x + wv.y*hv1.y;
            acc32 += wv.x*hv2.x + wv.y*hv2.y; acc33 += wv.x*hv3.x + wv.y*hv3.y;
        }
        {
            float* rbase = &red[kq * 256];
            int r0 = rq * 4, b0 = bq * 4;
            rbase[(r0+0)*16 + b0+0]=acc00; rbase[(r0+0)*16 + b0+1]=acc01; rbase[(r0+0)*16 + b0+2]=acc02; rbase[(r0+0)*16 + b0+3]=acc03;
            rbase[(r0+1)*16 + b0+0]=acc10; rbase[(r0+1)*16 + b0+1]=acc11; rbase[(r0+1)*16 + b0+2]=acc12; rbase[(r0+1)*16 + b0+3]=acc13;
            rbase[(r0+2)*16 + b0+0]=acc20; rbase[(r0+2)*16 + b0+1]=acc21; rbase[(r0+2)*16 + b0+2]=acc22; rbase[(r0+2)*16 + b0+3]=acc23;
            rbase[(r0+3)*16 + b0+0]=acc30; rbase[(r0+3)*16 + b0+1]=acc31; rbase[(r0+3)*16 + b0+2]=acc32; rbase[(r0+3)*16 + b0+3]=acc33;
        }
        __syncthreads();

        {
            float s = 0.0f;
#pragma unroll
            for (int k2 = 0; k2 < 16; k2++) s += red[k2 * 256 + xr * 16 + xb];
            pre[xr * 16 + xb] = s + xg_v;
        }
        __syncthreads();

        if (tid < 64) {
            int ul = tid >> 4, b = tid & 15;
            int ug = cta * 4 + ul;
            float iv = pre[(0  + ul) * 16 + b];
            float fv = pre[(4  + ul) * 16 + b];
            float gv = pre[(8  + ul) * 16 + b];
            float ov = pre[(12 + ul) * 16 + b];
            float c = cst[ul * 16 + b];
            c = sigf(fv) * c + sigf(iv) * tanhfast(gv);
            float hN = sigf(ov) * tanhfast(c);
            cst[ul * 16 + b] = c;
            g_hbuf[t & 1][b * 512 + ug] = hN;
            g_hs[(size_t)b * (SS * HH) + t * 512 + ug] = hN;
            if (t == SS - 1) {
                out_hc[b * 1024 + ug] = hN;
                out_hc[b * 1024 + 512 + ug] = c;
            }
        }

        if (t < SS - 1) {
            __threadfence();
            __syncthreads();
            if (tid == 0) {
                unsigned target = gen0 + (unsigned)t + 1u;
                unsigned a = atomicAdd(&g_cnt8[(cta & 7) << 8], 1u);
                if (a == 15u) {
                    unsigned m = atomicAdd(&g_master, 1u);
                    if (m == 7u) {
#pragma unroll
                        for (int q = 0; q < 8; q++)
                            atomicExch(&g_cnt8[q << 8], 0u);
                        atomicExch(&g_master, 0u);
                        __threadfence();
                        atomicAdd(&g_bar_gen, 1u);
                    }
                }
                while ((int)(*((volatile unsigned*)&g_bar_gen) - target) < 0) { }
            }
            __syncthreads();
            // reload h broadcast (bypass L1)
            const float2* src = (const float2*)(&g_hbuf[t & 1][0]);
            for (int i = tid; i < 4096; i += 256) {
                int b = i >> 8;
                int e2 = i & 255;
                float2 v = __ldcg(src + i);
                *(float2*)&hsm[b * HPAD + e2 * 2] = v;
            }
            __syncthreads();
        }
    }
}

// ============================================================================
// LayerNorm -> bf16 hi/lo split outputs
// ============================================================================
__global__ __launch_bounds__(128) void ln_kernel(
    const float* __restrict__ gamma, const float* __restrict__ beta)
{
    __shared__ float rs[4], rs2[4];
    const int m = blockIdx.x;
    const int tid = threadIdx.x;
    const float* row = g_hs + (size_t)m * 512;

    float4 v = *(const float4*)(row + tid * 4);
    float s  = v.x + v.y + v.z + v.w;
    float s2 = v.x * v.x + v.y * v.y + v.z * v.z + v.w * v.w;

    const int lane = tid & 31, w = tid >> 5;
#pragma unroll
    for (int o = 16; o; o >>= 1) {
        s  += __shfl_xor_sync(0xffffffffu, s, o);
        s2 += __shfl_xor_sync(0xffffffffu, s2, o);
    }
    if (lane == 0) { rs[w] = s; rs2[w] = s2; }
    __syncthreads();
    s  = rs[0] + rs[1] + rs[2] + rs[3];
    s2 = rs2[0] + rs2[1] + rs2[2] + rs2[3];

    float mu = s * (1.0f / 512.0f);
    float var = s2 * (1.0f / 512.0f) - mu * mu;
    float inv = rsqrtf(var + LNEPS);

    float4 g4 = *(const float4*)(gamma + tid * 4);
    float4 b4 = *(const float4*)(beta + tid * 4);
    float o0 = (v.x - mu) * inv * g4.x + b4.x;
    float o1 = (v.y - mu) * inv * g4.y + b4.y;
    float o2 = (v.z - mu) * inv * g4.z + b4.z;
    float o3 = (v.w - mu) * inv * g4.w + b4.w;

    __nv_bfloat16 h0, h1, h2, h3, l0, l1, l2, l3;
    split_bf16(o0, h0, l0); split_bf16(o1, h1, l1);
    split_bf16(o2, h2, l2); split_bf16(o3, h3, l3);

    __nv_bfloat162* hp = (__nv_bfloat162*)(g_nhi + (size_t)m * 512);
    __nv_bfloat162* lp = (__nv_bfloat162*)(g_nlo + (size_t)m * 512);
    hp[tid * 2 + 0] = __nv_bfloat162(h0, h1);
    hp[tid * 2 + 1] = __nv_bfloat162(h2, h3);
    lp[tid * 2 + 0] = __nv_bfloat162(l0, l1);
    lp[tid * 2 + 1] = __nv_bfloat162(l2, l3);
}

// ============================================================================
// mma.sync bf16-split GEMM: C[M x N] = A @ B^T + bias0 (+ bias1)
// CTA tile 128x256, warp tile 64x64, K=512 in 16 chunks of 32, 3-stage cp.async.
// MMA issue order is term-outermost: no back-to-back HMMAs on the same acc.
// ============================================================================
#define GS_STAGE 49152
#define FC_NCHUNK 16

__device__ __forceinline__ void ldsm_x4(uint32_t& r0, uint32_t& r1, uint32_t& r2,
                                        uint32_t& r3, uint32_t addr) {
    asm volatile("ldmatrix.sync.aligned.m8n8.x4.shared.b16 {%0,%1,%2,%3}, [%4];"
                 : "=r"(r0), "=r"(r1), "=r"(r2), "=r"(r3) : "r"(addr));
}

__device__ __forceinline__ void mma_bf16(float* c, const uint32_t* a, const uint32_t* b) {
    asm volatile(
        "mma.sync.aligned.m16n8k16.row.col.f32.bf16.bf16.f32 "
        "{%0,%1,%2,%3}, {%4,%5,%6,%7}, {%8,%9}, {%0,%1,%2,%3};"
        : "+f"(c[0]), "+f"(c[1]), "+f"(c[2]), "+f"(c[3])
        : "r"(a[0]), "r"(a[1]), "r"(a[2]), "r"(a[3]), "r"(b[0]), "r"(b[1]));
}

__global__ __launch_bounds__(256, 1) void gemm_mma(
    const __nv_bfloat16* __restrict__ Ahi, const __nv_bfloat16* __restrict__ Alo,
    const __nv_bfloat16* __restrict__ Bhi, const __nv_bfloat16* __restrict__ Blo,
    const float* __restrict__ bias0, const float* __restrict__ bias1,
    float* __restrict__ C, int N)
{
    extern __shared__ char smem[];
    const uint32_t sb = smem_u32(smem);
    const int tid = threadIdx.x;
    const int wid = tid >> 5;
    const int lane = tid & 31;
    const int m0 = blockIdx.x * 128;
    const int n0 = blockIdx.y * 256;
    const int warp_m = wid >> 2;   // 0..1 (64 m each)
    const int warp_n = wid & 3;    // 0..3 (64 n each)

    auto load_chunk = [&](int c) {
        const int k0 = c * 32;
        const uint32_t st = sb + (uint32_t)(c % 3) * GS_STAGE;
#pragma unroll
        for (int it = 0; it < 12; it++) {
            int i = it * 256 + tid;
            if (i < 1024) {
                int row = i >> 3;
                int g = i & 7;
                int part = g >> 2;
                int kg = g & 3;
                const __nv_bfloat16* src =
                    (part ? Alo : Ahi) + (size_t)(m0 + row) * 512 + k0 + kg * 8;
                uint32_t dst = st + (uint32_t)(row * 128) +
                               ((uint32_t)(g ^ (row & 7)) << 4);
                asm volatile("cp.async.cg.shared.global [%0], [%1], 16;" :: "r"(dst), "l"(src));
            } else {
                int li = i - 1024;
                int row = li >> 3;
                int g = li & 7;
                int part = g >> 2;
                int kg = g & 3;
                const __nv_bfloat16* src =
                    (part ? Blo : Bhi) + (size_t)(n0 + row) * 512 + k0 + kg * 8;
                uint32_t dst = st + 16384u + (uint32_t)(row * 128) +
                               ((uint32_t)(g ^ (row & 7)) << 4);
                asm volatile("cp.async.cg.shared.global [%0], [%1], 16;" :: "r"(dst), "l"(src));
            }
        }
        asm volatile("cp.async.commit_group;" ::: "memory");
    };

    load_chunk(0);
    load_chunk(1);

    const int t = lane >> 3, trow = lane & 7;
    const int a_mpart = (t & 1) * 8 + trow;
    const int a_gsel = t >> 1;
    uint32_t a_row_off[4]; uint32_t a_sw[4];
#pragma unroll
    for (int mf = 0; mf < 4; mf++) {
        int ml = warp_m * 64 + mf * 16 + a_mpart;
        a_row_off[mf] = (uint32_t)(ml * 128);
        a_sw[mf] = (uint32_t)(ml & 7);
    }
    const int b_fragsel = t >> 1;
    const int b_gsel = t & 1;
    uint32_t b_row_off[4]; uint32_t b_sw[4];
#pragma unroll
    for (int nf2 = 0; nf2 < 4; nf2++) {
        int nl = warp_n * 64 + (nf2 * 2 + b_fragsel) * 8 + trow;
        b_row_off[nf2] = (uint32_t)(nl * 128) + 16384u;
        b_sw[nf2] = (uint32_t)(nl & 7);
    }

    float acc[4][8][4];
#pragma unroll
    for (int i = 0; i < 4; i++)
#pragma unroll
        for (int j = 0; j < 8; j++)
#pragma unroll
            for (int r = 0; r < 4; r++) acc[i][j][r] = 0.0f;

    for (int c = 0; c < FC_NCHUNK; c++) {
        if (c < FC_NCHUNK - 1)
            asm volatile("cp.async.wait_group 1;" ::: "memory");
        else
            asm volatile("cp.async.wait_group 0;" ::: "memory");
        __syncthreads();
        if (c + 2 < FC_NCHUNK) load_chunk(c + 2);

        const uint32_t st = sb + (uint32_t)(c % 3) * GS_STAGE;
#pragma unroll
        for (int ks = 0; ks < 2; ks++) {
            uint32_t ah[4][4], al[4][4];
#pragma unroll
            for (int mf = 0; mf < 4; mf++) {
                uint32_t Ghi = (uint32_t)(ks * 2 + a_gsel);
                uint32_t Glo = Ghi + 4u;
                ldsm_x4(ah[mf][0], ah[mf][1], ah[mf][2], ah[mf][3],
                        st + a_row_off[mf] + ((Ghi ^ a_sw[mf]) << 4));
                ldsm_x4(al[mf][0], al[mf][1], al[mf][2], al[mf][3],
                        st + a_row_off[mf] + ((Glo ^ a_sw[mf]) << 4));
            }
#pragma unroll
            for (int nf2 = 0; nf2 < 4; nf2++) {
                uint32_t bh[2][2], bl[2][2];
                uint32_t Ghi = (uint32_t)(ks * 2 + b_gsel);
                uint32_t Glo = Ghi + 4u;
                ldsm_x4(bh[0][0], bh[0][1], bh[1][0], bh[1][1],
                        st + b_row_off[nf2] + ((Ghi ^ b_sw[nf2]) << 4));
                ldsm_x4(bl[0][0], bl[0][1], bl[1][0], bl[1][1],
                        st + b_row_off[nf2] + ((Glo ^ b_sw[nf2]) << 4));
                // term-outermost issue order: 8 independent accs between
                // consecutive writes to the same acc (hides HMMA latency).
#pragma unroll
                for (int mf = 0; mf < 4; mf++)
#pragma unroll
                    for (int j = 0; j < 2; j++)
                        mma_bf16(acc[mf][nf2 * 2 + j], ah[mf], bh[j]);   // hi*hi
#pragma unroll
                for (int mf = 0; mf < 4; mf++)
#pragma unroll
                    for (int j = 0; j < 2; j++)
                        mma_bf16(acc[mf][nf2 * 2 + j], al[mf], bh[j]);   // lo*hi
#pragma unroll
                for (int mf = 0; mf < 4; mf++)
#pragma unroll
                    for (int j = 0; j < 2; j++)
                        mma_bf16(acc[mf][nf2 * 2 + j], ah[mf], bl[j]);   // hi*lo
            }
        }
    }

    // ---- epilogue: direct global stores with bias ----
    const int lrow = lane >> 2;
    const int lcol = (lane & 3) * 2;
#pragma unroll
    for (int mf = 0; mf < 4; mf++) {
        int r0 = m0 + warp_m * 64 + mf * 16 + lrow;
        float* crow0 = C + (size_t)r0 * N;
        float* crow1 = crow0 + (size_t)8 * N;
#pragma unroll
        for (int nf = 0; nf < 8; nf++) {
            int cn = n0 + warp_n * 64 + nf * 8 + lcol;
            float b0 = __ldg(bias0 + cn);
            float b1 = __ldg(bias0 + cn + 1);
            if (bias1) { b0 += __ldg(bias1 + cn); b1 += __ldg(bias1 + cn + 1); }
            float2 v0 = { acc[mf][nf][0] + b0, acc[mf][nf][1] + b1 };
            float2 v1 = { acc[mf][nf][2] + b0, acc[mf][nf][3] + b1 };
            *(float2*)(crow0 + cn) = v0;
            *(float2*)(crow1 + cn) = v1;
        }
    }
}

// ============================================================================
// launch
// ============================================================================
extern "C" void kernel_launch(void* const* d_in, const int* in_sizes, int n_in,
                              void* d_out, int out_size)
{
    const int*   x    = (const int*)d_in[0];
    const float* z    = (const float*)d_in[1];
    const float* emb  = (const float*)d_in[2];
    const float* W_ih = (const float*)d_in[3];
    const float* W_hh = (const float*)d_in[4];
    const float* b_ih = (const float*)d_in[5];
    const float* b_hh = (const float*)d_in[6];
    const float* ln_g = (const float*)d_in[7];
    const float* ln_b = (const float*)d_in[8];
    const float* fc_W = (const float*)d_in[9];
    const float* fc_b = (const float*)d_in[10];
    float* out = (float*)d_out;

    float* xg_p;
    __nv_bfloat16 *whi_p, *wlo_p, *ahi_p, *alo_p, *ihhi_p, *ihlo_p, *nhi_p, *nlo_p;
    cudaGetSymbolAddress((void**)&xg_p, g_xg);
    cudaGetSymbolAddress((void**)&whi_p, g_whi);
    cudaGetSymbolAddress((void**)&wlo_p, g_wlo);
    cudaGetSymbolAddress((void**)&ahi_p, g_ahi);
    cudaGetSymbolAddress((void**)&alo_p, g_alo);
    cudaGetSymbolAddress((void**)&ihhi_p, g_ihhi);
    cudaGetSymbolAddress((void**)&ihlo_p, g_ihlo);
    cudaGetSymbolAddress((void**)&nhi_p, g_nhi);
    cudaGetSymbolAddress((void**)&nlo_p, g_nlo);

    const int gemm_smem = 3 * GS_STAGE;   // 147456
    cudaFuncSetAttribute(gemm_mma, cudaFuncAttributeMaxDynamicSharedMemorySize, gemm_smem);

    // K0a: fc_W -> bf16 hi/lo
    conv_split<<<2048, 256>>>(fc_W, whi_p, wlo_p, (unsigned)(VV * HH / 4));
    // K0b: W_ih -> bf16 hi/lo
    conv_split<<<256, 256>>>(W_ih, ihhi_p, ihlo_p, (unsigned)(GG * EE / 4));
    // K0c: gathered embedding -> bf16 hi/lo
    conv_emb<<<SS * BB, 128>>>(emb, x);

    // K1: input-side gate GEMM on tensor cores -> g_xg
    {
        dim3 grid((SS * BB) / 128, GG / 256);  // (16, 8) — single wave
        gemm_mma<<<grid, 256, gemm_smem>>>(ahi_p, alo_p, ihhi_p, ihlo_p,
                                           b_ih, b_hh, xg_p, GG);
    }

    // K2: persistent LSTM recurrence
    {
        const int smem = (16 * HPAD * 2 + 4096 + 256 + 64) * 4;
        cudaFuncSetAttribute(lstm_kernel, cudaFuncAttributeMaxDynamicSharedMemorySize, smem);
        lstm_kernel<<<128, 256, smem>>>(W_hh, z, out + (size_t)BB * SS * VV);
    }

    // K3: layernorm -> bf16 hi/lo
    ln_kernel<<<BB * SS, 128>>>(ln_g, ln_b);

    // K4: FC logits GEMM on tensor cores
    {
        dim3 grid((SS * BB) / 128, VV / 256);  // (16, 125)
        gemm_mma<<<grid, 256, gemm_smem>>>(nhi_p, nlo_p, whi_p, wlo_p,
                                           fc_b, nullptr, out, VV);
    }
}